// round 14
// baseline (speedup 1.0000x reference)
#include <cuda_runtime.h>
#include <cstdint>
#include <math.h>

#define B_ 32
#define C_ 64
#define M_ 9216
#define KSPLIT 12
#define KPC (M_ / KSPLIT)      // 768 k per CTA
#define KCH 32                 // k-chunk width (floats)
#define NCHK (KPC / KCH)       // 24 chunks
#define NPAIR (NCHK / 2)       // 12 pair-iterations
#define SMS 36                 // gram smem row stride
#define NSS 68                 // ns smem row stride
#define DSMEM ((4 * 64 * NSS + 96) * 4)   // 70016 B: covers gram stage (36 KB) and NS buffers

typedef unsigned long long ull;

// Scratch (no allocs allowed)
__device__ __align__(16) float g_gram_part[KSPLIT * B_ * C_ * C_];
__device__ __align__(16) float g_sum_part[KSPLIT * B_ * C_];
__device__ float g_gate[B_ * C_];
__device__ int g_count[B_];   // zero-init; self-resetting per launch

__device__ __forceinline__ void mma_tf32(float (&d)[4], const uint32_t a[4], const uint32_t b[2]) {
    asm volatile(
        "mma.sync.aligned.m16n8k8.row.col.f32.tf32.tf32.f32 "
        "{%0,%1,%2,%3}, {%4,%5,%6,%7}, {%8,%9}, {%0,%1,%2,%3};"
        : "+f"(d[0]), "+f"(d[1]), "+f"(d[2]), "+f"(d[3])
        : "r"(a[0]), "r"(a[1]), "r"(a[2]), "r"(a[3]), "r"(b[0]), "r"(b[1]));
}
__device__ __forceinline__ uint32_t smem_u32(const void* p) {
    uint32_t a;
    asm("{ .reg .u64 t; cvta.to.shared.u64 t, %1; cvt.u32.u64 %0, t; }" : "=r"(a) : "l"(p));
    return a;
}
__device__ __forceinline__ void cp16(uint32_t dst, const float* src) {
    asm volatile("cp.async.cg.shared.global [%0], [%1], 16;" :: "r"(dst), "l"(src) : "memory");
}
#define CP_COMMIT() asm volatile("cp.async.commit_group;" ::: "memory")
template <int N>
__device__ __forceinline__ void cp_wait() {
    asm volatile("cp.async.wait_group %0;" :: "n"(N) : "memory");
}

// ---------------------------------------------------------------------------
// NS matmul helpers (R8 shape: 8 warps, 32x16 tile per warp, raw f32 operands)
// ---------------------------------------------------------------------------
__device__ __forceinline__ void mm64t(float acc[2][2][4],
                                      const float* __restrict__ A,
                                      const float* __restrict__ B,
                                      int m0, int n0, int lq, int lr) {
    const uint32_t* UA = reinterpret_cast<const uint32_t*>(A);
    const uint32_t* UB = reinterpret_cast<const uint32_t*>(B);
#pragma unroll
    for (int mg = 0; mg < 2; mg++)
#pragma unroll
        for (int ng = 0; ng < 2; ng++)
#pragma unroll
            for (int e = 0; e < 4; e++) acc[mg][ng][e] = 0.f;
#pragma unroll
    for (int k8 = 0; k8 < 8; k8++) {
        const int k0 = 8 * k8;
        uint32_t a[2][4], b[2][2];
#pragma unroll
        for (int mg = 0; mg < 2; mg++) {
            int r = m0 + 16 * mg + lq;
            a[mg][0] = UA[r * NSS + k0 + lr];
            a[mg][1] = UA[(r + 8) * NSS + k0 + lr];
            a[mg][2] = UA[r * NSS + k0 + 4 + lr];
            a[mg][3] = UA[(r + 8) * NSS + k0 + 4 + lr];
        }
#pragma unroll
        for (int ng = 0; ng < 2; ng++) {
            int cn = n0 + 8 * ng + lq;
            b[ng][0] = UB[(k0 + lr) * NSS + cn];
            b[ng][1] = UB[(k0 + 4 + lr) * NSS + cn];
        }
#pragma unroll
        for (int mg = 0; mg < 2; mg++)
#pragma unroll
            for (int ng = 0; ng < 2; ng++) mma_tf32(acc[mg][ng], a[mg], b[ng]);
    }
}

__device__ __forceinline__ void frag_store(const float acc[2][2][4], float* __restrict__ D,
                                           int m0, int n0, int lq, int lr) {
#pragma unroll
    for (int mg = 0; mg < 2; mg++)
#pragma unroll
        for (int ng = 0; ng < 2; ng++) {
            int r = m0 + 16 * mg + lq;
            int cc = n0 + 8 * ng + 2 * lr;
            D[r * NSS + cc]           = acc[mg][ng][0];
            D[r * NSS + cc + 1]       = acc[mg][ng][1];
            D[(r + 8) * NSS + cc]     = acc[mg][ng][2];
            D[(r + 8) * NSS + cc + 1] = acc[mg][ng][3];
        }
}

__device__ __forceinline__ void frag_store_zy(const float acc[2][2][4],
                                              const float* __restrict__ Y,
                                              float* __restrict__ D,
                                              int m0, int n0, int lq, int lr) {
#pragma unroll
    for (int mg = 0; mg < 2; mg++)
#pragma unroll
        for (int ng = 0; ng < 2; ng++) {
            int r = m0 + 16 * mg + lq;
            int cc = n0 + 8 * ng + 2 * lr;
            D[r * NSS + cc]           = 1.5f * Y[r * NSS + cc]           - 0.5f * acc[mg][ng][0];
            D[r * NSS + cc + 1]       = 1.5f * Y[r * NSS + cc + 1]       - 0.5f * acc[mg][ng][1];
            D[(r + 8) * NSS + cc]     = 1.5f * Y[(r + 8) * NSS + cc]     - 0.5f * acc[mg][ng][2];
            D[(r + 8) * NSS + cc + 1] = 1.5f * Y[(r + 8) * NSS + cc + 1] - 0.5f * acc[mg][ng][3];
        }
}

// ---------------------------------------------------------------------------
// Kernel 1: fused Gram + (last-CTA-per-batch) Newton-Schulz + MLP + gate.
// Gram phase = R12 config (cp.async, truncated-f32 tf32, 8 warps).
// ---------------------------------------------------------------------------
__global__ void __launch_bounds__(256) gram_ns(const float* __restrict__ x,
                                               const float* __restrict__ gw1,
                                               const float* __restrict__ gb1,
                                               const float* __restrict__ gw2,
                                               const float* __restrict__ gb2) {
    extern __shared__ __align__(16) float sm[];
    uint32_t* S = reinterpret_cast<uint32_t*>(sm);   // gram stage: 4 bufs of 64*SMS
    __shared__ int s_last;

    const int ks = blockIdx.x, bi = blockIdx.y;
    const int tid = threadIdx.x;
    const int w = tid >> 5, l = tid & 31;
    const int lq = l >> 2, lr = l & 3;
    const int qd = w >> 2, wq = w & 3;
    const int rbase = (wq >> 1) << 5, cbase = (wq & 1) << 5;

    const int lrow = tid >> 3;
    const int lj = tid & 7;
    const int jj = wq * 32 + l;
    const int crow = jj >> 1;
    const int choff = (jj & 1) * 16;

    const float* xb = x + ((size_t)bi * C_) * M_ + (size_t)ks * KPC + 4 * lj;
    const float* p0 = xb + (size_t)lrow * M_;
    const float* p1 = xb + (size_t)(lrow + 32) * M_;

    const uint32_t sbase = smem_u32(sm);
    const uint32_t d0 = sbase + (lrow * SMS + 4 * lj) * 4;
    const uint32_t d1 = sbase + ((lrow + 32) * SMS + 4 * lj) * 4;
    const uint32_t BUFB = 64 * SMS * 4;

    float acc[2][4][4];
#pragma unroll
    for (int mg = 0; mg < 2; mg++)
#pragma unroll
        for (int j = 0; j < 4; j++)
#pragma unroll
            for (int e = 0; e < 4; e++) acc[mg][j][e] = 0.f;
    float csum = 0.f;

#pragma unroll
    for (int t = 0; t < 2; t++) {
#pragma unroll
        for (int cc = 0; cc < 2; cc++) {
            const int ch = 2 * t + cc;
            const uint32_t boff = (2 * (t & 1) + cc) * BUFB;
            cp16(d0 + boff, p0 + (size_t)ch * KCH);
            cp16(d1 + boff, p1 + (size_t)ch * KCH);
        }
        CP_COMMIT();
    }

    for (int t = 0; t < NPAIR; t++) {
        cp_wait<1>();
        __syncthreads();

        const uint32_t* UH = S + (2 * (t & 1) + qd) * (64 * SMS);
#pragma unroll
        for (int k8 = 0; k8 < 4; k8++) {
            const int k0 = 8 * k8;
            uint32_t a[2][4];
#pragma unroll
            for (int mg = 0; mg < 2; mg++) {
                int r = rbase + 16 * mg + lq;
                a[mg][0] = UH[r * SMS + k0 + lr];
                a[mg][1] = UH[(r + 8) * SMS + k0 + lr];
                a[mg][2] = UH[r * SMS + k0 + 4 + lr];
                a[mg][3] = UH[(r + 8) * SMS + k0 + 4 + lr];
            }
            uint32_t b[4][2];
#pragma unroll
            for (int j = 0; j < 4; j++) {
                int cn = cbase + 8 * j + lq;
                b[j][0] = UH[cn * SMS + k0 + lr];
                b[j][1] = UH[cn * SMS + k0 + 4 + lr];
            }
#pragma unroll
            for (int mg = 0; mg < 2; mg++)
#pragma unroll
                for (int j = 0; j < 4; j++) mma_tf32(acc[mg][j], a[mg], b[j]);
        }
        {
            const float* F = reinterpret_cast<const float*>(UH) + crow * SMS + choff;
#pragma unroll
            for (int i = 0; i < 4; i++) {
                float4 v = *reinterpret_cast<const float4*>(F + 4 * i);
                csum += v.x + v.y + v.z + v.w;
            }
        }
        __syncthreads();

        if (t + 2 < NPAIR) {
#pragma unroll
            for (int cc = 0; cc < 2; cc++) {
                const int ch = 2 * (t + 2) + cc;
                const uint32_t boff = (2 * (t & 1) + cc) * BUFB;
                cp16(d0 + boff, p0 + (size_t)ch * KCH);
                cp16(d1 + boff, p1 + (size_t)ch * KCH);
            }
        }
        CP_COMMIT();
    }

    // ---- gram epilogue: combine quadrant partials, write to gmem ----
    float* Pa = sm;                       // 64*65 floats (stage bufs 0-1)
    float* csA = sm + 2 * 64 * SMS;       // stage buf 2
    float* csB = csA + 64;
    if (qd == 0) {
#pragma unroll
        for (int mg = 0; mg < 2; mg++) {
            int r = rbase + 16 * mg + lq;
#pragma unroll
            for (int j = 0; j < 4; j++) {
                int cc = cbase + 8 * j + 2 * lr;
                Pa[r * 65 + cc]           = acc[mg][j][0];
                Pa[r * 65 + cc + 1]       = acc[mg][j][1];
                Pa[(r + 8) * 65 + cc]     = acc[mg][j][2];
                Pa[(r + 8) * 65 + cc + 1] = acc[mg][j][3];
            }
        }
    }
    csum += __shfl_xor_sync(0xffffffffu, csum, 1);
    if ((jj & 1) == 0) (qd ? csB : csA)[crow] = csum;
    __syncthreads();
    if (qd == 1) {
#pragma unroll
        for (int mg = 0; mg < 2; mg++) {
            int r = rbase + 16 * mg + lq;
#pragma unroll
            for (int j = 0; j < 4; j++) {
                int cc = cbase + 8 * j + 2 * lr;
                Pa[r * 65 + cc]           += acc[mg][j][0];
                Pa[r * 65 + cc + 1]       += acc[mg][j][1];
                Pa[(r + 8) * 65 + cc]     += acc[mg][j][2];
                Pa[(r + 8) * 65 + cc + 1] += acc[mg][j][3];
            }
        }
    }
    __syncthreads();
    {
        float* gp = g_gram_part + (((size_t)ks * B_ + bi) << 12);
        for (int e = tid; e < 4096; e += 256) {
            int r = e >> 6, cc = e & 63;
            gp[e] = Pa[r * 65 + cc];
        }
        if (tid < 64)
            g_sum_part[((size_t)ks * B_ + bi) * C_ + tid] = csA[tid] + csB[tid];
    }

    // ---- last-CTA election for this batch ----
    __threadfence();
    __syncthreads();
    if (tid == 0) {
        int old = atomicAdd(&g_count[bi], 1);
        s_last = (old == KSPLIT - 1);
    }
    __syncthreads();
    if (!s_last) return;
    if (tid == 0) g_count[bi] = 0;   // reset for next graph replay

    // =========================== NS phase (R8 body) ==========================
    float* bufA = sm;
    float* bufY = sm + 64 * NSS;
    float* bufZ = sm + 2 * 64 * NSS;
    float* bufT = sm + 3 * 64 * NSS;
    float* aux  = sm + 4 * 64 * NSS;

    const int m0 = (w & 1) * 32, n0 = (w >> 1) * 16;
    __syncthreads();   // smem reuse barrier

    {
        const float4* gp = reinterpret_cast<const float4*>(g_gram_part) + bi * 1024;
#pragma unroll
        for (int it = 0; it < 4; it++) {
            int e4 = it * 256 + tid;
            float4 a4 = make_float4(0.f, 0.f, 0.f, 0.f);
#pragma unroll
            for (int c = 0; c < KSPLIT; c++) {
                float4 v = gp[(size_t)c * (B_ * 1024) + e4];
                a4.x += v.x; a4.y += v.y; a4.z += v.z; a4.w += v.w;
            }
            int r = e4 >> 4, c4 = e4 & 15;
            *reinterpret_cast<float4*>(&bufA[r * NSS + 4 * c4]) = a4;
        }
    }
    if (tid < 64) {
        float s = 0.f;
#pragma unroll
        for (int c = 0; c < KSPLIT; c++) s += g_sum_part[(c * B_ + bi) * C_ + tid];
        aux[tid] = s * (1.0f / M_);
    }
    __syncthreads();
    {
        const float invM = 1.0f / M_;
        for (int e = tid; e < 4096; e += 256) {
            int r = e >> 6, c = e & 63;
            bufA[r * NSS + c] = bufA[r * NSS + c] * invM - aux[r] * aux[c];
        }
    }
    __syncthreads();
    if (tid < 32) {
        float t = bufA[tid * (NSS + 1)] + bufA[(tid + 32) * (NSS + 1)];
#pragma unroll
        for (int o = 16; o > 0; o >>= 1) t += __shfl_xor_sync(0xffffffffu, t, o);
        if (tid == 0) aux[64] = t;
    }
    __syncthreads();
    const float normA = aux[64];
    const float rnorm = 1.0f / normA;
    for (int e = tid; e < 4096; e += 256) {
        int r = e >> 6, c = e & 63;
        float a = bufA[r * NSS + c] * rnorm;
        bufA[r * NSS + c] = a;
        bufZ[r * NSS + c] = ((r == c) ? 1.5f : 0.0f) - 0.5f * a;
    }
    __syncthreads();
    {
        float acc2[2][2][4];
        mm64t(acc2, bufA, bufZ, m0, n0, lq, lr);
        frag_store(acc2, bufY, m0, n0, lq, lr);
    }
    __syncthreads();
    for (int it = 0; it < 3; it++) {
        {
            float acc2[2][2][4];
            mm64t(acc2, bufZ, bufY, m0, n0, lq, lr);
            frag_store_zy(acc2, bufY, bufT, m0, n0, lq, lr);
        }
        __syncthreads();
        {
            float accY[2][2][4], accZ[2][2][4];
            mm64t(accY, bufY, bufT, m0, n0, lq, lr);
            mm64t(accZ, bufT, bufZ, m0, n0, lq, lr);
            __syncthreads();
            frag_store(accY, bufY, m0, n0, lq, lr);
            frag_store(accZ, bufZ, m0, n0, lq, lr);
        }
        __syncthreads();
    }
    {
        float acc2[2][2][4];
        mm64t(acc2, bufZ, bufY, m0, n0, lq, lr);
        frag_store(acc2, bufT, m0, n0, lq, lr);
    }
    __syncthreads();
    {
        float acc2[2][2][4];
        mm64t(acc2, bufY, bufT, m0, n0, lq, lr);
        __syncthreads();
        frag_store_zy(acc2, bufY, bufA, m0, n0, lq, lr);
    }
    __syncthreads();
    const float scale_s = sqrtf(normA) * (1.0f / 64.0f);
    if (tid < 64) {
        float s = 0.f;
#pragma unroll 8
        for (int i = 0; i < 64; i++) s += bufA[i * NSS + tid];
        aux[tid] = s * scale_s;
    }
    __syncthreads();
    if (tid < 8) {
        float h = gb1[tid];
        const float* wr = gw1 + tid * 64;
        for (int j = 0; j < 64; j++) h += aux[j] * wr[j];
        aux[72 + tid] = fmaxf(h, 0.f);
    }
    __syncthreads();
    if (tid < 64) {
        float g = gb2[tid];
        const float* wr = gw2 + tid * 8;
#pragma unroll
        for (int r = 0; r < 8; r++) g += aux[72 + r] * wr[r];
        g_gate[bi * C_ + tid] = 1.0f / (1.0f + expf(-g));
    }
}

// ---------------------------------------------------------------------------
// Kernel 2: out = x * gate[b][c]
// ---------------------------------------------------------------------------
__global__ void __launch_bounds__(256) scale_kernel(const float* __restrict__ x,
                                                    float* __restrict__ out) {
    const int total4 = B_ * C_ * (M_ / 4);
    int i = blockIdx.x * blockDim.x + threadIdx.x;
    if (i >= total4) return;
    int bc = i / (M_ / 4);
    float g = __ldg(&g_gate[bc]);
    float4 v = reinterpret_cast<const float4*>(x)[i];
    v.x *= g; v.y *= g; v.z *= g; v.w *= g;
    reinterpret_cast<float4*>(out)[i] = v;
}

extern "C" void kernel_launch(void* const* d_in, const int* in_sizes, int n_in,
                              void* d_out, int out_size) {
    const float* x  = (const float*)d_in[0];
    const float* w1 = (const float*)d_in[1];
    const float* b1 = (const float*)d_in[2];
    const float* w2 = (const float*)d_in[3];
    const float* b2 = (const float*)d_in[4];
    float* out = (float*)d_out;

    static int attr_set = 0;
    if (!attr_set) {
        cudaFuncSetAttribute(gram_ns, cudaFuncAttributeMaxDynamicSharedMemorySize, DSMEM);
        attr_set = 1;
    }

    dim3 g1(KSPLIT, B_);
    gram_ns<<<g1, 256, DSMEM>>>(x, w1, b1, w2, b2);
    const int total4 = B_ * C_ * (M_ / 4);
    scale_kernel<<<(total4 + 255) / 256, 256>>>(x, out);
}

// round 15
// speedup vs baseline: 1.3228x; 1.3228x over previous
#include <cuda_runtime.h>
#include <cstdint>
#include <math.h>

#define B_ 32
#define C_ 64
#define M_ 9216
#define KSPLIT 12
#define KPC (M_ / KSPLIT)      // 768 k per CTA
#define KCH 32                 // k-chunk width (floats)
#define NCHK (KPC / KCH)       // 24 chunks
#define NPAIR (NCHK / 2)       // 12 pair-iterations
#define SMS 36                 // gram smem row stride
#define NSS 68                 // ns smem row stride
#define NS_SMEM ((4 * 64 * NSS + 96) * 4)

typedef unsigned long long ull;

// Scratch (no allocs allowed)
__device__ __align__(16) float g_gram_part[KSPLIT * B_ * C_ * C_];
__device__ __align__(16) float g_sum_part[KSPLIT * B_ * C_];
__device__ float g_gate[B_ * C_];

__device__ __forceinline__ uint32_t cvt_tf32(float v) {
    uint32_t r; asm("cvt.rna.tf32.f32 %0, %1;" : "=r"(r) : "f"(v)); return r;
}
__device__ __forceinline__ void mma_tf32(float (&d)[4], const uint32_t a[4], const uint32_t b[2]) {
    asm volatile(
        "mma.sync.aligned.m16n8k8.row.col.f32.tf32.tf32.f32 "
        "{%0,%1,%2,%3}, {%4,%5,%6,%7}, {%8,%9}, {%0,%1,%2,%3};"
        : "+f"(d[0]), "+f"(d[1]), "+f"(d[2]), "+f"(d[3])
        : "r"(a[0]), "r"(a[1]), "r"(a[2]), "r"(a[3]), "r"(b[0]), "r"(b[1]));
}

__device__ __forceinline__ void stage_chunk(uint32_t* dst, float4 v0, float4 v1,
                                            int lrow, int lj, float& cs0, float& cs1) {
    cs0 += v0.x + v0.y + v0.z + v0.w;
    cs1 += v1.x + v1.y + v1.z + v1.w;
    uint4 h0, h1;
    h0.x = cvt_tf32(v0.x); h0.y = cvt_tf32(v0.y); h0.z = cvt_tf32(v0.z); h0.w = cvt_tf32(v0.w);
    h1.x = cvt_tf32(v1.x); h1.y = cvt_tf32(v1.y); h1.z = cvt_tf32(v1.z); h1.w = cvt_tf32(v1.w);
    *reinterpret_cast<uint4*>(dst + lrow * SMS + 4 * lj) = h0;
    *reinterpret_cast<uint4*>(dst + (lrow + 32) * SMS + 4 * lj) = h1;
}

// ---------------------------------------------------------------------------
// Kernel 1: tensor-core Gram, tf32 single-pass (R8 config — best measured).
// 256 threads, 8 warps. Pairwise pipeline: warps 0-3 consume even chunks,
// warps 4-7 odd chunks; one barrier per two chunks. Each warp: 32x32 tile.
// ---------------------------------------------------------------------------
__global__ void __launch_bounds__(256, 3) gram_tc(const float* __restrict__ x) {
    __shared__ __align__(16) uint32_t s_stage[4][64 * SMS];  // 36 KB

    const int ks = blockIdx.x, bi = blockIdx.y;
    const int tid = threadIdx.x;
    const int w = tid >> 5, l = tid & 31;
    const int lq = l >> 2, lr = l & 3;
    const int qd = w >> 2, wq = w & 3;
    const int rbase = (wq >> 1) << 5, cbase = (wq & 1) << 5;

    const int lrow = tid >> 3;
    const int lj = tid & 7;

    const float* xb = x + ((size_t)bi * C_) * M_ + (size_t)ks * KPC + 4 * lj;
    const float* p0 = xb + (size_t)lrow * M_;
    const float* p1 = xb + (size_t)(lrow + 32) * M_;

    float acc[2][4][4];
#pragma unroll
    for (int mg = 0; mg < 2; mg++)
#pragma unroll
        for (int j = 0; j < 4; j++)
#pragma unroll
            for (int e = 0; e < 4; e++) acc[mg][j][e] = 0.f;
    float csum0 = 0.f, csum1 = 0.f;

    {
        float4 a0 = *reinterpret_cast<const float4*>(p0);
        float4 b0 = *reinterpret_cast<const float4*>(p1);
        float4 a1 = *reinterpret_cast<const float4*>(p0 + KCH);
        float4 b1 = *reinterpret_cast<const float4*>(p1 + KCH);
        stage_chunk(s_stage[0], a0, b0, lrow, lj, csum0, csum1);
        stage_chunk(s_stage[1], a1, b1, lrow, lj, csum0, csum1);
    }
    __syncthreads();

    for (int t = 0; t < NPAIR; t++) {
        float4 na0, nb0, na1, nb1;
        if (t + 1 < NPAIR) {
            const float* q0 = p0 + (size_t)(2 * t + 2) * KCH;
            const float* q1 = p1 + (size_t)(2 * t + 2) * KCH;
            na0 = *reinterpret_cast<const float4*>(q0);
            nb0 = *reinterpret_cast<const float4*>(q1);
            na1 = *reinterpret_cast<const float4*>(q0 + KCH);
            nb1 = *reinterpret_cast<const float4*>(q1 + KCH);
        }

        const uint32_t* UH = s_stage[2 * (t & 1) + qd];
#pragma unroll
        for (int k8 = 0; k8 < 4; k8++) {
            const int k0 = 8 * k8;
            uint32_t a[2][4];
#pragma unroll
            for (int mg = 0; mg < 2; mg++) {
                int r = rbase + 16 * mg + lq;
                a[mg][0] = UH[r * SMS + k0 + lr];
                a[mg][1] = UH[(r + 8) * SMS + k0 + lr];
                a[mg][2] = UH[r * SMS + k0 + 4 + lr];
                a[mg][3] = UH[(r + 8) * SMS + k0 + 4 + lr];
            }
            uint32_t b[4][2];
#pragma unroll
            for (int j = 0; j < 4; j++) {
                int cn = cbase + 8 * j + lq;
                b[j][0] = UH[cn * SMS + k0 + lr];
                b[j][1] = UH[cn * SMS + k0 + 4 + lr];
            }
#pragma unroll
            for (int mg = 0; mg < 2; mg++)
#pragma unroll
                for (int j = 0; j < 4; j++) mma_tf32(acc[mg][j], a[mg], b[j]);
        }

        if (t + 1 < NPAIR) {
            const int nb = 2 * ((t + 1) & 1);
            stage_chunk(s_stage[nb],     na0, nb0, lrow, lj, csum0, csum1);
            stage_chunk(s_stage[nb + 1], na1, nb1, lrow, lj, csum0, csum1);
        }
        __syncthreads();
    }

    // ---- epilogue: combine even/odd-chunk partials, write out
    float* Pa = reinterpret_cast<float*>(s_stage[0]);  // 64*65 floats, fits
    if (qd == 0) {
#pragma unroll
        for (int mg = 0; mg < 2; mg++) {
            int r = rbase + 16 * mg + lq;
#pragma unroll
            for (int j = 0; j < 4; j++) {
                int cc = cbase + 8 * j + 2 * lr;
                Pa[r * 65 + cc]           = acc[mg][j][0];
                Pa[r * 65 + cc + 1]       = acc[mg][j][1];
                Pa[(r + 8) * 65 + cc]     = acc[mg][j][2];
                Pa[(r + 8) * 65 + cc + 1] = acc[mg][j][3];
            }
        }
    }
    __syncthreads();
    if (qd == 1) {
#pragma unroll
        for (int mg = 0; mg < 2; mg++) {
            int r = rbase + 16 * mg + lq;
#pragma unroll
            for (int j = 0; j < 4; j++) {
                int cc = cbase + 8 * j + 2 * lr;
                Pa[r * 65 + cc]           += acc[mg][j][0];
                Pa[r * 65 + cc + 1]       += acc[mg][j][1];
                Pa[(r + 8) * 65 + cc]     += acc[mg][j][2];
                Pa[(r + 8) * 65 + cc + 1] += acc[mg][j][3];
            }
        }
    }
    {
        unsigned full = 0xffffffffu;
#pragma unroll
        for (int o = 4; o > 0; o >>= 1) {
            csum0 += __shfl_xor_sync(full, csum0, o);
            csum1 += __shfl_xor_sync(full, csum1, o);
        }
        if (lj == 0) {
            float* sp = g_sum_part + ((size_t)ks * B_ + bi) * C_;
            sp[lrow] = csum0;
            sp[lrow + 32] = csum1;
        }
    }
    __syncthreads();
    float* gp = g_gram_part + (((size_t)ks * B_ + bi) << 12);
    for (int e = tid; e < 4096; e += 256) {
        int r = e >> 6, cc = e & 63;
        gp[e] = Pa[r * 65 + cc];
    }
}

// ---------------------------------------------------------------------------
// NS matmul on tensor cores: warp owns 32x16 tile; raw f32 operands
// (HW truncates to tf32 inside mma — validated rel_err 0.0).
// ---------------------------------------------------------------------------
__device__ __forceinline__ void mm64t(float acc[2][2][4],
                                      const float* __restrict__ A,
                                      const float* __restrict__ B,
                                      int m0, int n0, int lq, int lr) {
    const uint32_t* UA = reinterpret_cast<const uint32_t*>(A);
    const uint32_t* UB = reinterpret_cast<const uint32_t*>(B);
#pragma unroll
    for (int mg = 0; mg < 2; mg++)
#pragma unroll
        for (int ng = 0; ng < 2; ng++)
#pragma unroll
            for (int e = 0; e < 4; e++) acc[mg][ng][e] = 0.f;
#pragma unroll
    for (int k8 = 0; k8 < 8; k8++) {
        const int k0 = 8 * k8;
        uint32_t a[2][4], b[2][2];
#pragma unroll
        for (int mg = 0; mg < 2; mg++) {
            int r = m0 + 16 * mg + lq;
            a[mg][0] = UA[r * NSS + k0 + lr];
            a[mg][1] = UA[(r + 8) * NSS + k0 + lr];
            a[mg][2] = UA[r * NSS + k0 + 4 + lr];
            a[mg][3] = UA[(r + 8) * NSS + k0 + 4 + lr];
        }
#pragma unroll
        for (int ng = 0; ng < 2; ng++) {
            int cn = n0 + 8 * ng + lq;
            b[ng][0] = UB[(k0 + lr) * NSS + cn];
            b[ng][1] = UB[(k0 + 4 + lr) * NSS + cn];
        }
#pragma unroll
        for (int mg = 0; mg < 2; mg++)
#pragma unroll
            for (int ng = 0; ng < 2; ng++) mma_tf32(acc[mg][ng], a[mg], b[ng]);
    }
}

__device__ __forceinline__ void frag_store(const float acc[2][2][4], float* __restrict__ D,
                                           int m0, int n0, int lq, int lr) {
#pragma unroll
    for (int mg = 0; mg < 2; mg++)
#pragma unroll
        for (int ng = 0; ng < 2; ng++) {
            int r = m0 + 16 * mg + lq;
            int cc = n0 + 8 * ng + 2 * lr;
            D[r * NSS + cc]           = acc[mg][ng][0];
            D[r * NSS + cc + 1]       = acc[mg][ng][1];
            D[(r + 8) * NSS + cc]     = acc[mg][ng][2];
            D[(r + 8) * NSS + cc + 1] = acc[mg][ng][3];
        }
}

__device__ __forceinline__ void frag_store_zy(const float acc[2][2][4],
                                              const float* __restrict__ Y,
                                              float* __restrict__ D,
                                              int m0, int n0, int lq, int lr) {
#pragma unroll
    for (int mg = 0; mg < 2; mg++)
#pragma unroll
        for (int ng = 0; ng < 2; ng++) {
            int r = m0 + 16 * mg + lq;
            int cc = n0 + 8 * ng + 2 * lr;
            D[r * NSS + cc]           = 1.5f * Y[r * NSS + cc]           - 0.5f * acc[mg][ng][0];
            D[r * NSS + cc + 1]       = 1.5f * Y[r * NSS + cc + 1]       - 0.5f * acc[mg][ng][1];
            D[(r + 8) * NSS + cc]     = 1.5f * Y[(r + 8) * NSS + cc]     - 0.5f * acc[mg][ng][2];
            D[(r + 8) * NSS + cc + 1] = 1.5f * Y[(r + 8) * NSS + cc + 1] - 0.5f * acc[mg][ng][3];
        }
}

// ---------------------------------------------------------------------------
// Kernel 2: reduce partials -> cov -> Newton-Schulz (tensor-core) -> MLP
// ---------------------------------------------------------------------------
__global__ void __launch_bounds__(256) ns_kernel(const float* __restrict__ gw1,
                                                 const float* __restrict__ gb1,
                                                 const float* __restrict__ gw2,
                                                 const float* __restrict__ gb2) {
    extern __shared__ __align__(16) float sm[];
    float* bufA = sm;
    float* bufY = sm + 64 * NSS;
    float* bufZ = sm + 2 * 64 * NSS;
    float* bufT = sm + 3 * 64 * NSS;
    float* aux  = sm + 4 * 64 * NSS;

    const int bi  = blockIdx.x;
    const int tid = threadIdx.x;
    const int w = tid >> 5, l = tid & 31;
    const int lq = l >> 2, lr = l & 3;
    const int m0 = (w & 1) * 32, n0 = (w >> 1) * 16;

    {
        const float4* gp = reinterpret_cast<const float4*>(g_gram_part) + bi * 1024;
#pragma unroll
        for (int it = 0; it < 4; it++) {
            int e4 = it * 256 + tid;
            float4 a4 = make_float4(0.f, 0.f, 0.f, 0.f);
#pragma unroll
            for (int c = 0; c < KSPLIT; c++) {
                float4 v = gp[(size_t)c * (B_ * 1024) + e4];
                a4.x += v.x; a4.y += v.y; a4.z += v.z; a4.w += v.w;
            }
            int r = e4 >> 4, c4 = e4 & 15;
            *reinterpret_cast<float4*>(&bufA[r * NSS + 4 * c4]) = a4;
        }
    }
    if (tid < 64) {
        float s = 0.f;
#pragma unroll
        for (int c = 0; c < KSPLIT; c++) s += g_sum_part[(c * B_ + bi) * C_ + tid];
        aux[tid] = s * (1.0f / M_);
    }
    __syncthreads();
    {
        const float invM = 1.0f / M_;
        for (int e = tid; e < 4096; e += 256) {
            int r = e >> 6, c = e & 63;
            bufA[r * NSS + c] = bufA[r * NSS + c] * invM - aux[r] * aux[c];
        }
    }
    __syncthreads();
    if (tid < 32) {
        float t = bufA[tid * (NSS + 1)] + bufA[(tid + 32) * (NSS + 1)];
#pragma unroll
        for (int o = 16; o > 0; o >>= 1) t += __shfl_xor_sync(0xffffffffu, t, o);
        if (tid == 0) aux[64] = t;
    }
    __syncthreads();
    const float normA = aux[64];
    const float rnorm = 1.0f / normA;
    for (int e = tid; e < 4096; e += 256) {
        int r = e >> 6, c = e & 63;
        float a = bufA[r * NSS + c] * rnorm;
        bufA[r * NSS + c] = a;
        bufZ[r * NSS + c] = ((r == c) ? 1.5f : 0.0f) - 0.5f * a;
    }
    __syncthreads();
    {
        float acc[2][2][4];
        mm64t(acc, bufA, bufZ, m0, n0, lq, lr);
        frag_store(acc, bufY, m0, n0, lq, lr);
    }
    __syncthreads();
    for (int it = 0; it < 3; it++) {
        {
            float acc[2][2][4];
            mm64t(acc, bufZ, bufY, m0, n0, lq, lr);
            frag_store_zy(acc, bufY, bufT, m0, n0, lq, lr);
        }
        __syncthreads();
        {
            float accY[2][2][4], accZ[2][2][4];
            mm64t(accY, bufY, bufT, m0, n0, lq, lr);
            mm64t(accZ, bufT, bufZ, m0, n0, lq, lr);
            __syncthreads();
            frag_store(accY, bufY, m0, n0, lq, lr);
            frag_store(accZ, bufZ, m0, n0, lq, lr);
        }
        __syncthreads();
    }
    {
        float acc[2][2][4];
        mm64t(acc, bufZ, bufY, m0, n0, lq, lr);
        frag_store(acc, bufT, m0, n0, lq, lr);
    }
    __syncthreads();
    {
        float acc[2][2][4];
        mm64t(acc, bufY, bufT, m0, n0, lq, lr);
        __syncthreads();
        frag_store_zy(acc, bufY, bufA, m0, n0, lq, lr);
    }
    __syncthreads();
    const float scale_s = sqrtf(normA) * (1.0f / 64.0f);
    if (tid < 64) {
        float s = 0.f;
#pragma unroll 8
        for (int i = 0; i < 64; i++) s += bufA[i * NSS + tid];
        aux[tid] = s * scale_s;
    }
    __syncthreads();
    if (tid < 8) {
        float h = gb1[tid];
        const float* wr = gw1 + tid * 64;
        for (int j = 0; j < 64; j++) h += aux[j] * wr[j];
        aux[72 + tid] = fmaxf(h, 0.f);
    }
    __syncthreads();
    if (tid < 64) {
        float g = gb2[tid];
        const float* wr = gw2 + tid * 8;
#pragma unroll
        for (int r = 0; r < 8; r++) g += aux[72 + r] * wr[r];
        g_gate[bi * C_ + tid] = 1.0f / (1.0f + expf(-g));
    }
}

// ---------------------------------------------------------------------------
// Kernel 3: out = x * gate[b][c]
// ---------------------------------------------------------------------------
__global__ void __launch_bounds__(256) scale_kernel(const float* __restrict__ x,
                                                    float* __restrict__ out) {
    const int total4 = B_ * C_ * (M_ / 4);
    int i = blockIdx.x * blockDim.x + threadIdx.x;
    if (i >= total4) return;
    int bc = i / (M_ / 4);
    float g = __ldg(&g_gate[bc]);
    float4 v = reinterpret_cast<const float4*>(x)[i];
    v.x *= g; v.y *= g; v.z *= g; v.w *= g;
    reinterpret_cast<float4*>(out)[i] = v;
}

extern "C" void kernel_launch(void* const* d_in, const int* in_sizes, int n_in,
                              void* d_out, int out_size) {
    const float* x  = (const float*)d_in[0];
    const float* w1 = (const float*)d_in[1];
    const float* b1 = (const float*)d_in[2];
    const float* w2 = (const float*)d_in[3];
    const float* b2 = (const float*)d_in[4];
    float* out = (float*)d_out;

    static int ns_attr_set = 0;
    if (!ns_attr_set) {
        cudaFuncSetAttribute(ns_kernel, cudaFuncAttributeMaxDynamicSharedMemorySize, NS_SMEM);
        ns_attr_set = 1;
    }

    dim3 g1(KSPLIT, B_);
    gram_tc<<<g1, 256>>>(x);
    ns_kernel<<<B_, 256, NS_SMEM>>>(w1, b1, w2, b2);
    const int total4 = B_ * C_ * (M_ / 4);
    scale_kernel<<<(total4 + 255) / 256, 256>>>(x, out);
}

// round 16
// speedup vs baseline: 1.3242x; 1.0010x over previous
#include <cuda_runtime.h>
#include <cstdint>
#include <math.h>

#define B_ 32
#define C_ 64
#define M_ 9216
#define KSPLIT 12
#define KPC (M_ / KSPLIT)      // 768 k per CTA
#define KCH 32                 // k-chunk width (floats)
#define NCHK (KPC / KCH)       // 24 chunks
#define NPAIR (NCHK / 2)       // 12 pair-iterations
#define SMS 36                 // gram smem row stride
#define NSS 68                 // ns smem row stride
#define NS_SMEM ((4 * 64 * NSS + 96) * 4)

typedef unsigned long long ull;

// Scratch (no allocs allowed)
__device__ __align__(16) float g_gram_part[KSPLIT * B_ * C_ * C_];
__device__ __align__(16) float g_sum_part[KSPLIT * B_ * C_];
__device__ float g_gate[B_ * C_];

__device__ __forceinline__ uint32_t cvt_tf32(float v) {
    uint32_t r; asm("cvt.rna.tf32.f32 %0, %1;" : "=r"(r) : "f"(v)); return r;
}
__device__ __forceinline__ void mma_tf32(float (&d)[4], const uint32_t a[4], const uint32_t b[2]) {
    asm volatile(
        "mma.sync.aligned.m16n8k8.row.col.f32.tf32.tf32.f32 "
        "{%0,%1,%2,%3}, {%4,%5,%6,%7}, {%8,%9}, {%0,%1,%2,%3};"
        : "+f"(d[0]), "+f"(d[1]), "+f"(d[2]), "+f"(d[3])
        : "r"(a[0]), "r"(a[1]), "r"(a[2]), "r"(a[3]), "r"(b[0]), "r"(b[1]));
}

__device__ __forceinline__ void stage_chunk(uint32_t* dst, float4 v0, float4 v1,
                                            int lrow, int lj, float& cs0, float& cs1) {
    cs0 += v0.x + v0.y + v0.z + v0.w;
    cs1 += v1.x + v1.y + v1.z + v1.w;
    uint4 h0, h1;
    h0.x = cvt_tf32(v0.x); h0.y = cvt_tf32(v0.y); h0.z = cvt_tf32(v0.z); h0.w = cvt_tf32(v0.w);
    h1.x = cvt_tf32(v1.x); h1.y = cvt_tf32(v1.y); h1.z = cvt_tf32(v1.z); h1.w = cvt_tf32(v1.w);
    *reinterpret_cast<uint4*>(dst + lrow * SMS + 4 * lj) = h0;
    *reinterpret_cast<uint4*>(dst + (lrow + 32) * SMS + 4 * lj) = h1;
}

// ---------------------------------------------------------------------------
// Kernel 1: tensor-core Gram, tf32 single-pass (best measured config).
// ---------------------------------------------------------------------------
__global__ void __launch_bounds__(256, 3) gram_tc(const float* __restrict__ x) {
    __shared__ __align__(16) uint32_t s_stage[4][64 * SMS];  // 36 KB

    const int ks = blockIdx.x, bi = blockIdx.y;
    const int tid = threadIdx.x;
    const int w = tid >> 5, l = tid & 31;
    const int lq = l >> 2, lr = l & 3;
    const int qd = w >> 2, wq = w & 3;
    const int rbase = (wq >> 1) << 5, cbase = (wq & 1) << 5;

    const int lrow = tid >> 3;
    const int lj = tid & 7;

    const float* xb = x + ((size_t)bi * C_) * M_ + (size_t)ks * KPC + 4 * lj;
    const float* p0 = xb + (size_t)lrow * M_;
    const float* p1 = xb + (size_t)(lrow + 32) * M_;

    float acc[2][4][4];
#pragma unroll
    for (int mg = 0; mg < 2; mg++)
#pragma unroll
        for (int j = 0; j < 4; j++)
#pragma unroll
            for (int e = 0; e < 4; e++) acc[mg][j][e] = 0.f;
    float csum0 = 0.f, csum1 = 0.f;

    {
        float4 a0 = *reinterpret_cast<const float4*>(p0);
        float4 b0 = *reinterpret_cast<const float4*>(p1);
        float4 a1 = *reinterpret_cast<const float4*>(p0 + KCH);
        float4 b1 = *reinterpret_cast<const float4*>(p1 + KCH);
        stage_chunk(s_stage[0], a0, b0, lrow, lj, csum0, csum1);
        stage_chunk(s_stage[1], a1, b1, lrow, lj, csum0, csum1);
    }
    __syncthreads();

    for (int t = 0; t < NPAIR; t++) {
        float4 na0, nb0, na1, nb1;
        if (t + 1 < NPAIR) {
            const float* q0 = p0 + (size_t)(2 * t + 2) * KCH;
            const float* q1 = p1 + (size_t)(2 * t + 2) * KCH;
            na0 = *reinterpret_cast<const float4*>(q0);
            nb0 = *reinterpret_cast<const float4*>(q1);
            na1 = *reinterpret_cast<const float4*>(q0 + KCH);
            nb1 = *reinterpret_cast<const float4*>(q1 + KCH);
        }

        const uint32_t* UH = s_stage[2 * (t & 1) + qd];
#pragma unroll
        for (int k8 = 0; k8 < 4; k8++) {
            const int k0 = 8 * k8;
            uint32_t a[2][4];
#pragma unroll
            for (int mg = 0; mg < 2; mg++) {
                int r = rbase + 16 * mg + lq;
                a[mg][0] = UH[r * SMS + k0 + lr];
                a[mg][1] = UH[(r + 8) * SMS + k0 + lr];
                a[mg][2] = UH[r * SMS + k0 + 4 + lr];
                a[mg][3] = UH[(r + 8) * SMS + k0 + 4 + lr];
            }
            uint32_t b[4][2];
#pragma unroll
            for (int j = 0; j < 4; j++) {
                int cn = cbase + 8 * j + lq;
                b[j][0] = UH[cn * SMS + k0 + lr];
                b[j][1] = UH[cn * SMS + k0 + 4 + lr];
            }
#pragma unroll
            for (int mg = 0; mg < 2; mg++)
#pragma unroll
                for (int j = 0; j < 4; j++) mma_tf32(acc[mg][j], a[mg], b[j]);
        }

        if (t + 1 < NPAIR) {
            const int nb = 2 * ((t + 1) & 1);
            stage_chunk(s_stage[nb],     na0, nb0, lrow, lj, csum0, csum1);
            stage_chunk(s_stage[nb + 1], na1, nb1, lrow, lj, csum0, csum1);
        }
        __syncthreads();
    }

    // ---- epilogue ----
    float* Pa = reinterpret_cast<float*>(s_stage[0]);
    if (qd == 0) {
#pragma unroll
        for (int mg = 0; mg < 2; mg++) {
            int r = rbase + 16 * mg + lq;
#pragma unroll
            for (int j = 0; j < 4; j++) {
                int cc = cbase + 8 * j + 2 * lr;
                Pa[r * 65 + cc]           = acc[mg][j][0];
                Pa[r * 65 + cc + 1]       = acc[mg][j][1];
                Pa[(r + 8) * 65 + cc]     = acc[mg][j][2];
                Pa[(r + 8) * 65 + cc + 1] = acc[mg][j][3];
            }
        }
    }
    __syncthreads();
    if (qd == 1) {
#pragma unroll
        for (int mg = 0; mg < 2; mg++) {
            int r = rbase + 16 * mg + lq;
#pragma unroll
            for (int j = 0; j < 4; j++) {
                int cc = cbase + 8 * j + 2 * lr;
                Pa[r * 65 + cc]           += acc[mg][j][0];
                Pa[r * 65 + cc + 1]       += acc[mg][j][1];
                Pa[(r + 8) * 65 + cc]     += acc[mg][j][2];
                Pa[(r + 8) * 65 + cc + 1] += acc[mg][j][3];
            }
        }
    }
    {
        unsigned full = 0xffffffffu;
#pragma unroll
        for (int o = 4; o > 0; o >>= 1) {
            csum0 += __shfl_xor_sync(full, csum0, o);
            csum1 += __shfl_xor_sync(full, csum1, o);
        }
        if (lj == 0) {
            float* sp = g_sum_part + ((size_t)ks * B_ + bi) * C_;
            sp[lrow] = csum0;
            sp[lrow + 32] = csum1;
        }
    }
    __syncthreads();
    float* gp = g_gram_part + (((size_t)ks * B_ + bi) << 12);
    for (int e = tid; e < 4096; e += 256) {
        int r = e >> 6, cc = e & 63;
        gp[e] = Pa[r * 65 + cc];
    }
}

// ---------------------------------------------------------------------------
// NS matmul on tensor cores (raw f32 operands, HW-truncated tf32)
// ---------------------------------------------------------------------------
__device__ __forceinline__ void mm64t(float acc[2][2][4],
                                      const float* __restrict__ A,
                                      const float* __restrict__ B,
                                      int m0, int n0, int lq, int lr) {
    const uint32_t* UA = reinterpret_cast<const uint32_t*>(A);
    const uint32_t* UB = reinterpret_cast<const uint32_t*>(B);
#pragma unroll
    for (int mg = 0; mg < 2; mg++)
#pragma unroll
        for (int ng = 0; ng < 2; ng++)
#pragma unroll
            for (int e = 0; e < 4; e++) acc[mg][ng][e] = 0.f;
#pragma unroll
    for (int k8 = 0; k8 < 8; k8++) {
        const int k0 = 8 * k8;
        uint32_t a[2][4], b[2][2];
#pragma unroll
        for (int mg = 0; mg < 2; mg++) {
            int r = m0 + 16 * mg + lq;
            a[mg][0] = UA[r * NSS + k0 + lr];
            a[mg][1] = UA[(r + 8) * NSS + k0 + lr];
            a[mg][2] = UA[r * NSS + k0 + 4 + lr];
            a[mg][3] = UA[(r + 8) * NSS + k0 + 4 + lr];
        }
#pragma unroll
        for (int ng = 0; ng < 2; ng++) {
            int cn = n0 + 8 * ng + lq;
            b[ng][0] = UB[(k0 + lr) * NSS + cn];
            b[ng][1] = UB[(k0 + 4 + lr) * NSS + cn];
        }
#pragma unroll
        for (int mg = 0; mg < 2; mg++)
#pragma unroll
            for (int ng = 0; ng < 2; ng++) mma_tf32(acc[mg][ng], a[mg], b[ng]);
    }
}

__device__ __forceinline__ void frag_store(const float acc[2][2][4], float* __restrict__ D,
                                           int m0, int n0, int lq, int lr) {
#pragma unroll
    for (int mg = 0; mg < 2; mg++)
#pragma unroll
        for (int ng = 0; ng < 2; ng++) {
            int r = m0 + 16 * mg + lq;
            int cc = n0 + 8 * ng + 2 * lr;
            D[r * NSS + cc]           = acc[mg][ng][0];
            D[r * NSS + cc + 1]       = acc[mg][ng][1];
            D[(r + 8) * NSS + cc]     = acc[mg][ng][2];
            D[(r + 8) * NSS + cc + 1] = acc[mg][ng][3];
        }
}

__device__ __forceinline__ void frag_store_zy(const float acc[2][2][4],
                                              const float* __restrict__ Y,
                                              float* __restrict__ D,
                                              int m0, int n0, int lq, int lr) {
#pragma unroll
    for (int mg = 0; mg < 2; mg++)
#pragma unroll
        for (int ng = 0; ng < 2; ng++) {
            int r = m0 + 16 * mg + lq;
            int cc = n0 + 8 * ng + 2 * lr;
            D[r * NSS + cc]           = 1.5f * Y[r * NSS + cc]           - 0.5f * acc[mg][ng][0];
            D[r * NSS + cc + 1]       = 1.5f * Y[r * NSS + cc + 1]       - 0.5f * acc[mg][ng][1];
            D[(r + 8) * NSS + cc]     = 1.5f * Y[(r + 8) * NSS + cc]     - 0.5f * acc[mg][ng][2];
            D[(r + 8) * NSS + cc + 1] = 1.5f * Y[(r + 8) * NSS + cc + 1] - 0.5f * acc[mg][ng][3];
        }
}

// ---------------------------------------------------------------------------
// Kernel 2: reduce partials -> cov -> Newton-Schulz (tensor-core) -> MLP
// ---------------------------------------------------------------------------
__global__ void __launch_bounds__(256) ns_kernel(const float* __restrict__ gw1,
                                                 const float* __restrict__ gb1,
                                                 const float* __restrict__ gw2,
                                                 const float* __restrict__ gb2) {
    extern __shared__ __align__(16) float sm[];
    float* bufA = sm;
    float* bufY = sm + 64 * NSS;
    float* bufZ = sm + 2 * 64 * NSS;
    float* bufT = sm + 3 * 64 * NSS;
    float* aux  = sm + 4 * 64 * NSS;

    const int bi  = blockIdx.x;
    const int tid = threadIdx.x;
    const int w = tid >> 5, l = tid & 31;
    const int lq = l >> 2, lr = l & 3;
    const int m0 = (w & 1) * 32, n0 = (w >> 1) * 16;

    {
        const float4* gp = reinterpret_cast<const float4*>(g_gram_part) + bi * 1024;
#pragma unroll
        for (int it = 0; it < 4; it++) {
            int e4 = it * 256 + tid;
            float4 a4 = make_float4(0.f, 0.f, 0.f, 0.f);
#pragma unroll
            for (int c = 0; c < KSPLIT; c++) {
                float4 v = gp[(size_t)c * (B_ * 1024) + e4];
                a4.x += v.x; a4.y += v.y; a4.z += v.z; a4.w += v.w;
            }
            int r = e4 >> 4, c4 = e4 & 15;
            *reinterpret_cast<float4*>(&bufA[r * NSS + 4 * c4]) = a4;
        }
    }
    if (tid < 64) {
        float s = 0.f;
#pragma unroll
        for (int c = 0; c < KSPLIT; c++) s += g_sum_part[(c * B_ + bi) * C_ + tid];
        aux[tid] = s * (1.0f / M_);
    }
    __syncthreads();
    {
        const float invM = 1.0f / M_;
        for (int e = tid; e < 4096; e += 256) {
            int r = e >> 6, c = e & 63;
            bufA[r * NSS + c] = bufA[r * NSS + c] * invM - aux[r] * aux[c];
        }
    }
    __syncthreads();
    if (tid < 32) {
        float t = bufA[tid * (NSS + 1)] + bufA[(tid + 32) * (NSS + 1)];
#pragma unroll
        for (int o = 16; o > 0; o >>= 1) t += __shfl_xor_sync(0xffffffffu, t, o);
        if (tid == 0) aux[64] = t;
    }
    __syncthreads();
    const float normA = aux[64];
    const float rnorm = 1.0f / normA;
    for (int e = tid; e < 4096; e += 256) {
        int r = e >> 6, c = e & 63;
        float a = bufA[r * NSS + c] * rnorm;
        bufA[r * NSS + c] = a;
        bufZ[r * NSS + c] = ((r == c) ? 1.5f : 0.0f) - 0.5f * a;
    }
    __syncthreads();
    {
        float acc[2][2][4];
        mm64t(acc, bufA, bufZ, m0, n0, lq, lr);
        frag_store(acc, bufY, m0, n0, lq, lr);
    }
    __syncthreads();
    for (int it = 0; it < 3; it++) {
        {
            float acc[2][2][4];
            mm64t(acc, bufZ, bufY, m0, n0, lq, lr);
            frag_store_zy(acc, bufY, bufT, m0, n0, lq, lr);
        }
        __syncthreads();
        {
            float accY[2][2][4], accZ[2][2][4];
            mm64t(accY, bufY, bufT, m0, n0, lq, lr);
            mm64t(accZ, bufT, bufZ, m0, n0, lq, lr);
            __syncthreads();
            frag_store(accY, bufY, m0, n0, lq, lr);
            frag_store(accZ, bufZ, m0, n0, lq, lr);
        }
        __syncthreads();
    }
    {
        float acc[2][2][4];
        mm64t(acc, bufZ, bufY, m0, n0, lq, lr);
        frag_store(acc, bufT, m0, n0, lq, lr);
    }
    __syncthreads();
    {
        float acc[2][2][4];
        mm64t(acc, bufY, bufT, m0, n0, lq, lr);
        __syncthreads();
        frag_store_zy(acc, bufY, bufA, m0, n0, lq, lr);
    }
    __syncthreads();
    const float scale_s = sqrtf(normA) * (1.0f / 64.0f);
    if (tid < 64) {
        float s = 0.f;
#pragma unroll 8
        for (int i = 0; i < 64; i++) s += bufA[i * NSS + tid];
        aux[tid] = s * scale_s;
    }
    __syncthreads();
    if (tid < 8) {
        float h = gb1[tid];
        const float* wr = gw1 + tid * 64;
        for (int j = 0; j < 64; j++) h += aux[j] * wr[j];
        aux[72 + tid] = fmaxf(h, 0.f);
    }
    __syncthreads();
    if (tid < 64) {
        float g = gb2[tid];
        const float* wr = gw2 + tid * 8;
#pragma unroll
        for (int r = 0; r < 8; r++) g += aux[72 + r] * wr[r];
        g_gate[bi * C_ + tid] = 1.0f / (1.0f + expf(-g));
    }
}

// ---------------------------------------------------------------------------
// Kernel 3: out = x * gate[b][c]. Streaming (evict-first) stores keep x's
// L2 residency (left by gram) intact.
// ---------------------------------------------------------------------------
__global__ void __launch_bounds__(256) scale_kernel(const float* __restrict__ x,
                                                    float* __restrict__ out) {
    const int total4 = B_ * C_ * (M_ / 4);
    int i = blockIdx.x * blockDim.x + threadIdx.x;
    if (i >= total4) return;
    int bc = i / (M_ / 4);
    float g = __ldg(&g_gate[bc]);
    float4 v = reinterpret_cast<const float4*>(x)[i];
    v.x *= g; v.y *= g; v.z *= g; v.w *= g;
    __stcs(reinterpret_cast<float4*>(out) + i, v);
}

extern "C" void kernel_launch(void* const* d_in, const int* in_sizes, int n_in,
                              void* d_out, int out_size) {
    const float* x  = (const float*)d_in[0];
    const float* w1 = (const float*)d_in[1];
    const float* b1 = (const float*)d_in[2];
    const float* w2 = (const float*)d_in[3];
    const float* b2 = (const float*)d_in[4];
    float* out = (float*)d_out;

    static int ns_attr_set = 0;
    if (!ns_attr_set) {
        cudaFuncSetAttribute(ns_kernel, cudaFuncAttributeMaxDynamicSharedMemorySize, NS_SMEM);
        ns_attr_set = 1;
    }

    dim3 g1(KSPLIT, B_);
    gram_tc<<<g1, 256>>>(x);
    ns_kernel<<<B_, 256, NS_SMEM>>>(w1, b1, w2, b2);
    const int total4 = B_ * C_ * (M_ / 4);
    scale_kernel<<<(total4 + 255) / 256, 256>>>(x, out);
}